// round 1
// baseline (speedup 1.0000x reference)
#include <cuda_runtime.h>
#include <math.h>

// Problem constants
static constexpr int NB  = 2;
static constexpr int NL  = 1024;
static constexpr int NH  = 64;
static constexpr int NV  = 32000;
static constexpr int HID = 256;
static constexpr int NT  = NB * NL;      // 2048 tokens
static constexpr int KA  = 448;          // 64 freq + 64 cos + 64 sin + 256 hidden

// Scratch (device globals: allocation-free)
__device__ float g_At[KA * NT];          // K-major packed token features (448 x 2048)
__device__ float g_Bv[192 * NV];         // K-major packed vocab features (192 x 32000); Wv read directly
__device__ float g_v2[NV];
__device__ float g_f2[NT];
__device__ float g_lamp[NT];

__device__ __forceinline__ float gelu_exact(float x) {
    return 0.5f * x * (1.0f + erff(x * 0.7071067811865476f));
}

// ---------------------------------------------------------------------------
// Token prep: 4 tokens per block, 256 threads.
// Computes MLP (3 layers), f2, log1p(sum amps), and writes packed A rows:
//   rows [0,64)    = freqs (raw)
//   rows [64,128)  = cos(phase) * (0.5/64) * lamp
//   rows [128,192) = sin(phase) * (0.5/64) * lamp
//   rows [192,448) = 0.1 * x_final
// ---------------------------------------------------------------------------
__global__ void token_prep(const float* __restrict__ wave,
                           const float* __restrict__ W0, const float* __restrict__ b0,
                           const float* __restrict__ W1, const float* __restrict__ b1,
                           const float* __restrict__ W2, const float* __restrict__ b2,
                           const float* __restrict__ rw)
{
    __shared__ float sw[4][192];
    __shared__ float sx[4][256];
    __shared__ float sy[4][256];
    __shared__ float slamp[4];

    const int t0 = blockIdx.x * 4;
    const int j  = threadIdx.x;

    // load 4 wave rows (768 floats)
    for (int i = j; i < 4 * 192; i += 256) {
        int tok = i / 192, kk = i % 192;
        sw[tok][kk] = wave[(size_t)(t0 + tok) * 192 + kk];
    }
    __syncthreads();

    // per-token scalars (tiny serial reductions, 8 threads)
    if (j < 8) {
        int tok = j & 3;
        if (j < 4) {
            float s = 0.f;
            for (int h = 0; h < NH; h++) { float f = sw[tok][h]; s += f * f; }
            g_f2[t0 + tok] = s;
        } else {
            float s = 0.f;
            for (int h = 0; h < NH; h++) s += sw[tok][64 + h];
            float l = log1pf(s);
            slamp[tok] = l;
            g_lamp[t0 + tok] = l;
        }
    }

    // layer 0: 192 -> 256
    float acc0 = 0.f, acc1 = 0.f, acc2 = 0.f, acc3 = 0.f;
    float bb = b0[j];
    for (int k = 0; k < 192; k++) {
        float w = W0[k * 256 + j];
        acc0 = fmaf(sw[0][k], w, acc0);
        acc1 = fmaf(sw[1][k], w, acc1);
        acc2 = fmaf(sw[2][k], w, acc2);
        acc3 = fmaf(sw[3][k], w, acc3);
    }
    __syncthreads();
    sx[0][j] = gelu_exact(acc0 + bb);
    sx[1][j] = gelu_exact(acc1 + bb);
    sx[2][j] = gelu_exact(acc2 + bb);
    sx[3][j] = gelu_exact(acc3 + bb);
    __syncthreads();

    // layer 1: 256 -> 256 with residual rw[1]
    bb = b1[j];
    float r1 = rw[1];
    acc0 = acc1 = acc2 = acc3 = 0.f;
    for (int k = 0; k < 256; k++) {
        float w = W1[k * 256 + j];
        acc0 = fmaf(sx[0][k], w, acc0);
        acc1 = fmaf(sx[1][k], w, acc1);
        acc2 = fmaf(sx[2][k], w, acc2);
        acc3 = fmaf(sx[3][k], w, acc3);
    }
    sy[0][j] = gelu_exact(acc0 + bb) + r1 * sx[0][j];
    sy[1][j] = gelu_exact(acc1 + bb) + r1 * sx[1][j];
    sy[2][j] = gelu_exact(acc2 + bb) + r1 * sx[2][j];
    sy[3][j] = gelu_exact(acc3 + bb) + r1 * sx[3][j];
    __syncthreads();

    // layer 2: 256 -> 256 with residual rw[2]
    bb = b2[j];
    float r2 = rw[2];
    acc0 = acc1 = acc2 = acc3 = 0.f;
    for (int k = 0; k < 256; k++) {
        float w = W2[k * 256 + j];
        acc0 = fmaf(sy[0][k], w, acc0);
        acc1 = fmaf(sy[1][k], w, acc1);
        acc2 = fmaf(sy[2][k], w, acc2);
        acc3 = fmaf(sy[3][k], w, acc3);
    }
    {
        float z0 = gelu_exact(acc0 + bb) + r2 * sy[0][j];
        float z1 = gelu_exact(acc1 + bb) + r2 * sy[1][j];
        float z2 = gelu_exact(acc2 + bb) + r2 * sy[2][j];
        float z3 = gelu_exact(acc3 + bb) + r2 * sy[3][j];
        g_At[(size_t)(192 + j) * NT + (t0 + 0)] = 0.1f * z0;
        g_At[(size_t)(192 + j) * NT + (t0 + 1)] = 0.1f * z1;
        g_At[(size_t)(192 + j) * NT + (t0 + 2)] = 0.1f * z2;
        g_At[(size_t)(192 + j) * NT + (t0 + 3)] = 0.1f * z3;
    }

    // freq + trig rows: thread j -> token i = j>>6, h = j&63
    {
        int i = j >> 6, h = j & 63;
        float f  = sw[i][h];
        float ph = sw[i][128 + h];
        float sc = 0.0078125f * slamp[i];     // (0.5/64) * log1p(amp_energy)
        float sn, cs;
        sincosf(ph, &sn, &cs);
        g_At[(size_t)h          * NT + (t0 + i)] = f;
        g_At[(size_t)(64 + h)   * NT + (t0 + i)] = cs * sc;
        g_At[(size_t)(128 + h)  * NT + (t0 + i)] = sn * sc;
    }
}

// ---------------------------------------------------------------------------
// Vocab prep
// ---------------------------------------------------------------------------
__global__ void vocab_v2_kernel(const float* __restrict__ vf)
{
    int v = blockIdx.x * 256 + threadIdx.x;
    if (v >= NV) return;
    const float* r = vf + (size_t)v * NH;
    float s = 0.f;
    #pragma unroll
    for (int h = 0; h < NH; h++) s = fmaf(r[h], r[h], s);
    g_v2[v] = s;
}

// Tiled transpose + trig: writes g_Bv rows [0,64)=vf^T, [64,128)=cos(vp)^T, [128,192)=sin(vp)^T
__global__ void vocab_pack(const float* __restrict__ vf, const float* __restrict__ vp)
{
    __shared__ float tf[32][33], tc[32][33], ts[32][33];
    const int v0 = blockIdx.x * 32;
    const int h0 = blockIdx.y * 32;
    const int tx = threadIdx.x, ty = threadIdx.y;   // (32, 8)
    #pragma unroll
    for (int r = 0; r < 4; r++) {
        int vv = v0 + ty + r * 8, hh = h0 + tx;
        float f = vf[(size_t)vv * NH + hh];
        float p = vp[(size_t)vv * NH + hh];
        float sn, cs; sincosf(p, &sn, &cs);
        tf[ty + r * 8][tx] = f;
        tc[ty + r * 8][tx] = cs;
        ts[ty + r * 8][tx] = sn;
    }
    __syncthreads();
    #pragma unroll
    for (int r = 0; r < 4; r++) {
        int hh = h0 + ty + r * 8, vv = v0 + tx;
        g_Bv[(size_t)hh         * NV + vv] = tf[tx][ty + r * 8];
        g_Bv[(size_t)(64 + hh)  * NV + vv] = tc[tx][ty + r * 8];
        g_Bv[(size_t)(128 + hh) * NV + vv] = ts[tx][ty + r * 8];
    }
}

// ---------------------------------------------------------------------------
// Main fused GEMM: 64x128 tile, KC=16, 256 threads, 8x4 per thread.
// Two accumulators: accC over K [0,64) (cross), accT over K [64,448) (coh+syn).
// ---------------------------------------------------------------------------
static constexpr int TM = 64;
static constexpr int TN = 128;
static constexpr int KC = 16;

__global__ void __launch_bounds__(256)
spectral_gemm(const float* __restrict__ Wv, const float* __restrict__ bv,
              float* __restrict__ out)
{
    __shared__ float As[KC][TM];
    __shared__ float Bs[KC][TN];

    const int v0 = blockIdx.x * TN;
    const int t0 = blockIdx.y * TM;
    const int tid = threadIdx.x;
    const int col0 = (tid & 31) * 4;   // 0..124
    const int row0 = (tid >> 5) * 8;   // 0..56
    const int lk = tid >> 4;           // 0..15  (K row of the tile this thread loads)
    const int lc = (tid & 15) * 4;     // 0..60

    float accC[8][4];
    float accT[8][4];
    #pragma unroll
    for (int r = 0; r < 8; r++)
        #pragma unroll
        for (int c = 0; c < 4; c++) { accC[r][c] = 0.f; accT[r][c] = 0.f; }

#define LOAD_TILE(K0) {                                                              \
        int kk = (K0) + lk;                                                          \
        *(float4*)&As[lk][lc] =                                                      \
            *(const float4*)(g_At + (size_t)kk * NT + t0 + lc);                      \
        const float* br = (kk < 192) ? (g_Bv + (size_t)kk * NV)                      \
                                     : (Wv + (size_t)(kk - 192) * NV);               \
        *(float4*)&Bs[lk][lc]      = *(const float4*)(br + v0 + lc);                 \
        *(float4*)&Bs[lk][lc + 64] = *(const float4*)(br + v0 + lc + 64);            \
    }

#define MMA_STEP(ACC) {                                                              \
        _Pragma("unroll")                                                            \
        for (int k = 0; k < KC; k++) {                                               \
            float4 bq = *(float4*)&Bs[k][col0];                                      \
            float4 a0 = *(float4*)&As[k][row0];                                      \
            float4 a1 = *(float4*)&As[k][row0 + 4];                                  \
            float av[8] = {a0.x, a0.y, a0.z, a0.w, a1.x, a1.y, a1.z, a1.w};          \
            float bw[4] = {bq.x, bq.y, bq.z, bq.w};                                  \
            _Pragma("unroll")                                                        \
            for (int r = 0; r < 8; r++)                                              \
                _Pragma("unroll")                                                    \
                for (int c = 0; c < 4; c++)                                          \
                    ACC[r][c] = fmaf(av[r], bw[c], ACC[r][c]);                       \
        }                                                                            \
    }

    // Phase 1: cross term, K chunks 0..3  (k in [0,64))
    for (int ch = 0; ch < 4; ch++) {
        LOAD_TILE(ch * KC);
        __syncthreads();
        MMA_STEP(accC);
        __syncthreads();
    }
    // Phase 2: coherence + synthesis, K chunks 4..27  (k in [64,448))
    for (int ch = 4; ch < 28; ch++) {
        LOAD_TILE(ch * KC);
        __syncthreads();
        MMA_STEP(accT);
        __syncthreads();
    }
#undef LOAD_TILE
#undef MMA_STEP

    // Epilogue
    float f2r[8], lam[8];
    #pragma unroll
    for (int r = 0; r < 8; r++) {
        f2r[r] = g_f2[t0 + row0 + r];
        lam[r] = g_lamp[t0 + row0 + r];
    }
    float v2c[4], bvc[4];
    #pragma unroll
    for (int c = 0; c < 4; c++) {
        v2c[c] = g_v2[v0 + col0 + c];
        bvc[c] = 0.1f * bv[v0 + col0 + c];
    }
    #pragma unroll
    for (int r = 0; r < 8; r++) {
        float4 o;
        float* po = (float*)&o;
        #pragma unroll
        for (int c = 0; c < 4; c++) {
            float d2 = f2r[r] + v2c[c] - 2.0f * accC[r][c];
            po[c] = accT[r][c] - sqrtf(fmaxf(d2, 0.0f)) * lam[r] + bvc[c];
        }
        *(float4*)(out + (size_t)(t0 + row0 + r) * NV + v0 + col0) = o;
    }
}

// ---------------------------------------------------------------------------
extern "C" void kernel_launch(void* const* d_in, const int* in_sizes, int n_in,
                              void* d_out, int out_size)
{
    const float* wave = (const float*)d_in[0];   // (2,1024,192)
    const float* vf   = (const float*)d_in[1];   // (32000,64)
    const float* vp   = (const float*)d_in[2];   // (32000,64)
    const float* W0   = (const float*)d_in[3];   // (192,256)
    const float* b0   = (const float*)d_in[4];
    const float* W1   = (const float*)d_in[5];   // (256,256)
    const float* b1   = (const float*)d_in[6];
    const float* W2   = (const float*)d_in[7];   // (256,256)
    const float* b2   = (const float*)d_in[8];
    const float* Wv   = (const float*)d_in[9];   // (256,32000) — already K-major for GEMM
    const float* bv   = (const float*)d_in[10];  // (32000,)
    const float* rw   = (const float*)d_in[11];  // (3,)
    float* out = (float*)d_out;

    token_prep<<<NT / 4, 256>>>(wave, W0, b0, W1, b1, W2, b2, rw);
    vocab_v2_kernel<<<(NV + 255) / 256, 256>>>(vf);
    vocab_pack<<<dim3(NV / 32, NH / 32), dim3(32, 8)>>>(vf, vp);
    spectral_gemm<<<dim3(NV / TN, NT / TM), 256>>>(Wv, bv, out);
}